// round 2
// baseline (speedup 1.0000x reference)
#include <cuda_runtime.h>

#define BD 4
#define TD 50
#define DD 512
#define SRCN 400
#define SENTN 16
#define WORDN 40
#define SJ 1040         // SRC + SENTS*WORDS
#define BT 200          // B*T
#define WQPAD 256       // padded rows per Wq set
#define UHROWS 4224     // 4*(16+400+640)

// ---- scratch (device globals; no allocation allowed) ----
__device__ float g_wq[3 * WQPAD * DD];     // set0=word, set1=sent, set2=pass; row = b*50+t
__device__ float g_uh[UHROWS * DD];        // rows: [0,64)=sent, [64,1664)=src, [1664,4224)=word
__device__ float g_sent[BT * SENTN];
__device__ float g_align[BT * SJ];
__device__ float g_p[BT * SJ];

__device__ __forceinline__ float tanh_acc(float x) {
    // accurate fast tanh: tanh(x) = sign(x) * (1 - 2/(exp(2|x|)+1)); inf-safe
    float a = fabsf(x);
    float e = __expf(2.0f * a);
    float r = 1.0f - __fdividef(2.0f, e + 1.0f);
    return copysignf(r, x);
}

// ============================================================
// GEMM 1: wq = source @ Wq + bq  for 3 weight sets, M padded to 256/set
// ============================================================
__global__ __launch_bounds__(256) void wq_gemm(
    const float* __restrict__ source,
    const float* __restrict__ W0, const float* __restrict__ W1, const float* __restrict__ W2,
    const float* __restrict__ b0, const float* __restrict__ b1, const float* __restrict__ b2)
{
    __shared__ float As[16][64];
    __shared__ float Bs[16][64];
    int tid = threadIdx.x;
    int m0 = blockIdx.y * 64;
    int n0 = blockIdx.x * 64;
    int set = m0 >> 8;
    const float* W    = (set == 0) ? W0 : (set == 1 ? W1 : W2);
    const float* bias = (set == 0) ? b0 : (set == 1 ? b1 : b2);

    int lr = tid >> 2;                 // 0..63  A row in tile
    int lk = (tid & 3) << 2;           // 0..12  A k offset
    int rloc = (m0 & 255) + lr;        // row within set
    int arow = rloc < BT ? rloc : (BT - 1);
    const float* aptr = source + arow * DD + lk;
    int br = tid >> 4;                 // 0..15
    int bc = (tid & 15) << 2;          // 0..60
    const float* bptr = W + br * DD + n0 + bc;

    int ty = tid >> 4, tx = tid & 15;
    float acc[4][4] = {};

    for (int k0 = 0; k0 < DD; k0 += 16) {
        float4 av = *(const float4*)(aptr + k0);
        float4 bv = *(const float4*)(bptr + (size_t)k0 * DD);
        As[lk + 0][lr] = av.x; As[lk + 1][lr] = av.y;
        As[lk + 2][lr] = av.z; As[lk + 3][lr] = av.w;
        *(float4*)&Bs[br][bc] = bv;
        __syncthreads();
#pragma unroll
        for (int kk = 0; kk < 16; kk++) {
            float4 a  = *(const float4*)&As[kk][ty << 2];
            float4 bb = *(const float4*)&Bs[kk][tx << 2];
            acc[0][0] += a.x * bb.x; acc[0][1] += a.x * bb.y; acc[0][2] += a.x * bb.z; acc[0][3] += a.x * bb.w;
            acc[1][0] += a.y * bb.x; acc[1][1] += a.y * bb.y; acc[1][2] += a.y * bb.z; acc[1][3] += a.y * bb.w;
            acc[2][0] += a.z * bb.x; acc[2][1] += a.z * bb.y; acc[2][2] += a.z * bb.z; acc[2][3] += a.z * bb.w;
            acc[3][0] += a.w * bb.x; acc[3][1] += a.w * bb.y; acc[3][2] += a.w * bb.z; acc[3][3] += a.w * bb.w;
        }
        __syncthreads();
    }

    float4 bb = *(const float4*)(bias + n0 + (tx << 2));
#pragma unroll
    for (int i = 0; i < 4; i++) {
        int rs = (m0 & 255) + (ty << 2) + i;
        if (rs < BT) {
            int grow = m0 + (ty << 2) + i;
            float4 o;
            o.x = acc[i][0] + bb.x; o.y = acc[i][1] + bb.y;
            o.z = acc[i][2] + bb.z; o.w = acc[i][3] + bb.w;
            *(float4*)&g_wq[(size_t)grow * DD + n0 + (tx << 2)] = o;
        }
    }
}

// ============================================================
// GEMM 2: uh = gathered_bank @ Uc  (segments: sent | src | word)
// ============================================================
__device__ __forceinline__ const float* uh_src_row(int r,
    const float* sentb, const float* srcb, const float* wordb)
{
    if (r < 64)   { int b = r >> 4, j = r & 15; return sentb + ((size_t)(j * BD + b)) * DD; }
    if (r < 1664) { int q = r - 64; int b = q / SRCN, i = q - b * SRCN;
                    return srcb + ((size_t)(i * BD + b)) * DD; }
    int q = r - 1664; int b = q / 640; int rem = q - b * 640;
    int s = rem / WORDN, w = rem - s * WORDN;
    return wordb + ((size_t)((w * BD + b) * SENTN + s)) * DD;
}

__global__ __launch_bounds__(256) void uh_gemm(
    const float* __restrict__ sentb, const float* __restrict__ srcb, const float* __restrict__ wordb,
    const float* __restrict__ Usent, const float* __restrict__ Upass, const float* __restrict__ Uword)
{
    __shared__ float As[16][64];
    __shared__ float Bs[16][64];
    __shared__ const float* rowp[64];
    int tid = threadIdx.x;
    int m0 = blockIdx.y * 64;
    int n0 = blockIdx.x * 64;
    const float* W = (m0 < 64) ? Usent : (m0 < 1664 ? Upass : Uword);
    if (tid < 64) rowp[tid] = uh_src_row(m0 + tid, sentb, srcb, wordb);
    __syncthreads();

    int lr = tid >> 2;
    int lk = (tid & 3) << 2;
    const float* aptr = rowp[lr] + lk;
    int br = tid >> 4;
    int bc = (tid & 15) << 2;
    const float* bptr = W + br * DD + n0 + bc;

    int ty = tid >> 4, tx = tid & 15;
    float acc[4][4] = {};

    for (int k0 = 0; k0 < DD; k0 += 16) {
        float4 av = *(const float4*)(aptr + k0);
        float4 bv = *(const float4*)(bptr + (size_t)k0 * DD);
        As[lk + 0][lr] = av.x; As[lk + 1][lr] = av.y;
        As[lk + 2][lr] = av.z; As[lk + 3][lr] = av.w;
        *(float4*)&Bs[br][bc] = bv;
        __syncthreads();
#pragma unroll
        for (int kk = 0; kk < 16; kk++) {
            float4 a  = *(const float4*)&As[kk][ty << 2];
            float4 bb = *(const float4*)&Bs[kk][tx << 2];
            acc[0][0] += a.x * bb.x; acc[0][1] += a.x * bb.y; acc[0][2] += a.x * bb.z; acc[0][3] += a.x * bb.w;
            acc[1][0] += a.y * bb.x; acc[1][1] += a.y * bb.y; acc[1][2] += a.y * bb.z; acc[1][3] += a.y * bb.w;
            acc[2][0] += a.z * bb.x; acc[2][1] += a.z * bb.y; acc[2][2] += a.z * bb.z; acc[2][3] += a.z * bb.w;
            acc[3][0] += a.w * bb.x; acc[3][1] += a.w * bb.y; acc[3][2] += a.w * bb.z; acc[3][3] += a.w * bb.w;
        }
        __syncthreads();
    }
#pragma unroll
    for (int i = 0; i < 4; i++) {
        int grow = m0 + (ty << 2) + i;
        float4 o;
        o.x = acc[i][0]; o.y = acc[i][1]; o.z = acc[i][2]; o.w = acc[i][3];
        *(float4*)&g_uh[(size_t)grow * DD + n0 + (tx << 2)] = o;
    }
}

// ============================================================
// sentence-level scores: g_sent[b*50+t][j] = sum_d v_sent[d]*tanh(wq_sent + uh_sent)
// ============================================================
__global__ __launch_bounds__(128) void sent_kernel(const float* __restrict__ v_sent)
{
    int row = blockIdx.x;          // b*50 + t
    int b = row / TD;
    int lane = threadIdx.x & 31, warp = threadIdx.x >> 5;  // 4 warps
    const float* wq = g_wq + (size_t)WQPAD * DD + (size_t)row * DD;  // set 1 = sent
#pragma unroll
    for (int jj = 0; jj < 4; jj++) {
        int j = warp * 4 + jj;
        const float* uh = g_uh + (size_t)(b * 16 + j) * DD;
        float acc = 0.f;
        for (int d = lane; d < DD; d += 32)
            acc += v_sent[d] * tanh_acc(wq[d] + uh[d]);
#pragma unroll
        for (int o = 16; o; o >>= 1) acc += __shfl_xor_sync(0xffffffffu, acc, o);
        if (lane == 0) g_sent[row * SENTN + j] = acc;
    }
}

// ============================================================
// main score kernel: align[b,t,:] (src | hier-word), masked
// grid (13 j-tiles of 80, 4 t-tiles of 16, B)
// ============================================================
#define SC_CHUNK 64
__global__ __launch_bounds__(256) void score_kernel(
    const float* __restrict__ v_pass, const float* __restrict__ v_word,
    const int* __restrict__ src_len, const int* __restrict__ word_len)
{
    __shared__ float wq_s[16 * SC_CHUNK];
    __shared__ float uh_s[80 * (SC_CHUNK + 1)];
    __shared__ float v_s[SC_CHUNK];
    int tid = threadIdx.x;
    int jt = blockIdx.x, tt = blockIdx.y, b = blockIdx.z;
    int t0 = tt * 16;
    bool is_src = (jt < 5);
    const float* wqb = g_wq + (size_t)(is_src ? 2 : 0) * WQPAD * DD + (size_t)(b * TD) * DD;
    int uh0 = is_src ? (64 + b * SRCN + jt * 80) : (1664 + b * 640 + (jt - 5) * 80);
    const float* v = is_src ? v_pass : v_word;

    int tx = tid & 15, ty = tid >> 4;
    float acc[5] = {0.f, 0.f, 0.f, 0.f, 0.f};

    for (int d0 = 0; d0 < DD; d0 += SC_CHUNK) {
        __syncthreads();
        for (int i = tid; i < 16 * SC_CHUNK; i += 256) {
            int r = i / SC_CHUNK, c = i - r * SC_CHUNK;
            wq_s[r * SC_CHUNK + c] = wqb[(size_t)(t0 + r) * DD + d0 + c];  // padded rows are zero, discarded later
        }
        for (int i = tid; i < 80 * SC_CHUNK; i += 256) {
            int r = i / SC_CHUNK, c = i - r * SC_CHUNK;
            uh_s[r * (SC_CHUNK + 1) + c] = g_uh[(size_t)(uh0 + r) * DD + d0 + c];
        }
        if (tid < SC_CHUNK) v_s[tid] = v[d0 + tid];
        __syncthreads();
#pragma unroll 2
        for (int d = 0; d < SC_CHUNK; d++) {
            float w  = wq_s[ty * SC_CHUNK + d];
            float vv = v_s[d];
#pragma unroll
            for (int u = 0; u < 5; u++) {
                float x = w + uh_s[(tx + 16 * u) * (SC_CHUNK + 1) + d];
                acc[u] += vv * tanh_acc(x);
            }
        }
    }

    int t = t0 + ty;
    if (t < TD) {
        float* arow = g_align + (size_t)(b * TD + t) * SJ;
#pragma unroll
        for (int u = 0; u < 5; u++) {
            int jl = tx + 16 * u;
            if (is_src) {
                int j = jt * 80 + jl;
                arow[j] = (j < src_len[b]) ? acc[u] : -1e30f;
            } else {
                int jw = (jt - 5) * 80 + jl;
                int s = jw / WORDN, w = jw - s * WORDN;
                float sc = acc[u] * g_sent[(b * TD + t) * SENTN + s];
                arow[SRCN + jw] = (w < word_len[b * SENTN + s]) ? sc : -1e30f;
            }
        }
    }
}

// ============================================================
// softmax over 1040 per (b,t)
// ============================================================
__global__ __launch_bounds__(256) void softmax_kernel()
{
    __shared__ float red[256];
    int row = blockIdx.x, tid = threadIdx.x;
    const float* a = g_align + (size_t)row * SJ;
    float m = -3.4e38f;
    for (int j = tid; j < SJ; j += 256) m = fmaxf(m, a[j]);
    red[tid] = m; __syncthreads();
    for (int o = 128; o; o >>= 1) { if (tid < o) red[tid] = fmaxf(red[tid], red[tid + o]); __syncthreads(); }
    m = red[0]; __syncthreads();
    float s = 0.f;
    for (int j = tid; j < SJ; j += 256) s += __expf(a[j] - m);
    red[tid] = s; __syncthreads();
    for (int o = 128; o; o >>= 1) { if (tid < o) red[tid] += red[tid + o]; __syncthreads(); }
    float inv = 1.0f / red[0];
    for (int j = tid; j < SJ; j += 256) g_p[(size_t)row * SJ + j] = __expf(a[j] - m) * inv;
}

// ============================================================
// context: c[b,t,d] = sum_j p[b,t,j] * mem[b,j,d]   (gathered GEMM)
// grid (16 d-tiles of 32, B)
// ============================================================
__global__ __launch_bounds__(256) void context_kernel(
    const float* __restrict__ srcb, const float* __restrict__ wordb, float* __restrict__ out)
{
    __shared__ float p_s[50 * 80];
    __shared__ float m_s[80 * 33];
    int tid = threadIdx.x;
    int b = blockIdx.y;
    int d0 = blockIdx.x * 32;
    int tx = tid & 31, ty = tid >> 5;   // 32 x 8
    float acc[7] = {};

    for (int j0 = 0; j0 < SJ; j0 += 80) {
        __syncthreads();
        for (int i = tid; i < 50 * 80; i += 256) {
            int r = i / 80, c = i - r * 80;
            p_s[i] = g_p[(size_t)(b * TD + r) * SJ + j0 + c];
        }
        for (int i = tid; i < 80 * 32; i += 256) {
            int r = i >> 5, c = i & 31;
            int j = j0 + r;
            const float* mp;
            if (j < SRCN) mp = srcb + (size_t)(j * BD + b) * DD;
            else { int jw = j - SRCN; int s = jw / WORDN, w = jw - s * WORDN;
                   mp = wordb + (size_t)((w * BD + b) * SENTN + s) * DD; }
            m_s[r * 33 + c] = mp[d0 + c];
        }
        __syncthreads();
        for (int j = 0; j < 80; j++) {
            float mv = m_s[j * 33 + tx];
#pragma unroll
            for (int q = 0; q < 7; q++) {
                int t = ty + (q << 3);
                if (t < TD) acc[q] += p_s[t * 80 + j] * mv;
            }
        }
    }
#pragma unroll
    for (int q = 0; q < 7; q++) {
        int t = ty + (q << 3);
        if (t < TD) out[(size_t)(b * TD + t) * DD + d0 + tx] = acc[q];
    }
}

// ============================================================
extern "C" void kernel_launch(void* const* d_in, const int* in_sizes, int n_in,
                              void* d_out, int out_size)
{
    const float* source    = (const float*)d_in[0];
    const float* src_bank  = (const float*)d_in[1];
    const int*   src_len   = (const int*)  d_in[2];
    const float* sent_bank = (const float*)d_in[3];
    // d_in[4] = qa_sent_lengths (unused, matches reference)
    const float* word_bank = (const float*)d_in[5];
    const int*   word_len  = (const int*)  d_in[6];
    const float* Wq_word = (const float*)d_in[7];
    const float* bq_word = (const float*)d_in[8];
    const float* Uc_word = (const float*)d_in[9];
    const float* v_word  = (const float*)d_in[10];
    const float* Wq_sent = (const float*)d_in[11];
    const float* bq_sent = (const float*)d_in[12];
    const float* Uc_sent = (const float*)d_in[13];
    const float* v_sent  = (const float*)d_in[14];
    const float* Wq_pass = (const float*)d_in[15];
    const float* bq_pass = (const float*)d_in[16];
    const float* Uc_pass = (const float*)d_in[17];
    const float* v_pass  = (const float*)d_in[18];
    float* out = (float*)d_out;

    wq_gemm<<<dim3(8, 12), 256>>>(source, Wq_word, Wq_sent, Wq_pass, bq_word, bq_sent, bq_pass);
    uh_gemm<<<dim3(8, 66), 256>>>(sent_bank, src_bank, word_bank, Uc_sent, Uc_pass, Uc_word);
    sent_kernel<<<200, 128>>>(v_sent);
    score_kernel<<<dim3(13, 4, 4), 256>>>(v_pass, v_word, src_len, word_len);
    softmax_kernel<<<200, 256>>>();
    context_kernel<<<dim3(16, 4), 256>>>(src_bank, word_bank, out);
}

// round 3
// speedup vs baseline: 1.3912x; 1.3912x over previous
#include <cuda_runtime.h>

#define BD 4
#define TD 50
#define DD 512
#define SRCN 400
#define SENTN 16
#define WORDN 40
#define SJ 1040         // SRC + SENTS*WORDS
#define BT 200          // B*T
#define WQPAD 256       // padded rows per Wq set
#define UHROWS 4224     // 4*(16+400+640)

// ---- scratch (device globals; no allocation allowed) ----
__device__ float g_wq[3 * WQPAD * DD];     // set0=word, set1=sent, set2=pass; row = b*50+t
__device__ float g_uh[UHROWS * DD];        // rows: [0,64)=sent, [64,1664)=src, [1664,4224)=word
__device__ float g_sent[BT * SENTN];
__device__ float g_align0[BT * SJ];        // partial scores, d in [0,256)
__device__ float g_align1[BT * SJ];        // partial scores, d in [256,512)
__device__ float g_p[BT * SJ];

__device__ __forceinline__ float tanh_fast(float x) {
    float y;
    asm("tanh.approx.f32 %0, %1;" : "=f"(y) : "f"(x));
    return y;
}

// ============================================================
// GEMM 1: wq = source @ Wq + bq  for 3 weight sets, M padded to 256/set
// ============================================================
__global__ __launch_bounds__(256) void wq_gemm(
    const float* __restrict__ source,
    const float* __restrict__ W0, const float* __restrict__ W1, const float* __restrict__ W2,
    const float* __restrict__ b0, const float* __restrict__ b1, const float* __restrict__ b2)
{
    __shared__ float As[16][64];
    __shared__ float Bs[16][64];
    int tid = threadIdx.x;
    int m0 = blockIdx.y * 64;
    int n0 = blockIdx.x * 64;
    int set = m0 >> 8;
    const float* W    = (set == 0) ? W0 : (set == 1 ? W1 : W2);
    const float* bias = (set == 0) ? b0 : (set == 1 ? b1 : b2);

    int lr = tid >> 2;                 // 0..63  A row in tile
    int lk = (tid & 3) << 2;           // 0..12  A k offset
    int rloc = (m0 & 255) + lr;        // row within set
    int arow = rloc < BT ? rloc : (BT - 1);
    const float* aptr = source + arow * DD + lk;
    int br = tid >> 4;                 // 0..15
    int bc = (tid & 15) << 2;          // 0..60
    const float* bptr = W + br * DD + n0 + bc;

    int ty = tid >> 4, tx = tid & 15;
    float acc[4][4] = {};

    for (int k0 = 0; k0 < DD; k0 += 16) {
        float4 av = *(const float4*)(aptr + k0);
        float4 bv = *(const float4*)(bptr + (size_t)k0 * DD);
        As[lk + 0][lr] = av.x; As[lk + 1][lr] = av.y;
        As[lk + 2][lr] = av.z; As[lk + 3][lr] = av.w;
        *(float4*)&Bs[br][bc] = bv;
        __syncthreads();
#pragma unroll
        for (int kk = 0; kk < 16; kk++) {
            float4 a  = *(const float4*)&As[kk][ty << 2];
            float4 bb = *(const float4*)&Bs[kk][tx << 2];
            acc[0][0] += a.x * bb.x; acc[0][1] += a.x * bb.y; acc[0][2] += a.x * bb.z; acc[0][3] += a.x * bb.w;
            acc[1][0] += a.y * bb.x; acc[1][1] += a.y * bb.y; acc[1][2] += a.y * bb.z; acc[1][3] += a.y * bb.w;
            acc[2][0] += a.z * bb.x; acc[2][1] += a.z * bb.y; acc[2][2] += a.z * bb.z; acc[2][3] += a.z * bb.w;
            acc[3][0] += a.w * bb.x; acc[3][1] += a.w * bb.y; acc[3][2] += a.w * bb.z; acc[3][3] += a.w * bb.w;
        }
        __syncthreads();
    }

    float4 bb = *(const float4*)(bias + n0 + (tx << 2));
#pragma unroll
    for (int i = 0; i < 4; i++) {
        int rs = (m0 & 255) + (ty << 2) + i;
        if (rs < BT) {
            int grow = m0 + (ty << 2) + i;
            float4 o;
            o.x = acc[i][0] + bb.x; o.y = acc[i][1] + bb.y;
            o.z = acc[i][2] + bb.z; o.w = acc[i][3] + bb.w;
            *(float4*)&g_wq[(size_t)grow * DD + n0 + (tx << 2)] = o;
        }
    }
}

// ============================================================
// GEMM 2: uh = gathered_bank @ Uc  (segments: sent | src | word)
// ============================================================
__device__ __forceinline__ const float* uh_src_row(int r,
    const float* sentb, const float* srcb, const float* wordb)
{
    if (r < 64)   { int b = r >> 4, j = r & 15; return sentb + ((size_t)(j * BD + b)) * DD; }
    if (r < 1664) { int q = r - 64; int b = q / SRCN, i = q - b * SRCN;
                    return srcb + ((size_t)(i * BD + b)) * DD; }
    int q = r - 1664; int b = q / 640; int rem = q - b * 640;
    int s = rem / WORDN, w = rem - s * WORDN;
    return wordb + ((size_t)((w * BD + b) * SENTN + s)) * DD;
}

__global__ __launch_bounds__(256) void uh_gemm(
    const float* __restrict__ sentb, const float* __restrict__ srcb, const float* __restrict__ wordb,
    const float* __restrict__ Usent, const float* __restrict__ Upass, const float* __restrict__ Uword)
{
    __shared__ float As[16][64];
    __shared__ float Bs[16][64];
    __shared__ const float* rowp[64];
    int tid = threadIdx.x;
    int m0 = blockIdx.y * 64;
    int n0 = blockIdx.x * 64;
    const float* W = (m0 < 64) ? Usent : (m0 < 1664 ? Upass : Uword);
    if (tid < 64) rowp[tid] = uh_src_row(m0 + tid, sentb, srcb, wordb);
    __syncthreads();

    int lr = tid >> 2;
    int lk = (tid & 3) << 2;
    const float* aptr = rowp[lr] + lk;
    int br = tid >> 4;
    int bc = (tid & 15) << 2;
    const float* bptr = W + br * DD + n0 + bc;

    int ty = tid >> 4, tx = tid & 15;
    float acc[4][4] = {};

    for (int k0 = 0; k0 < DD; k0 += 16) {
        float4 av = *(const float4*)(aptr + k0);
        float4 bv = *(const float4*)(bptr + (size_t)k0 * DD);
        As[lk + 0][lr] = av.x; As[lk + 1][lr] = av.y;
        As[lk + 2][lr] = av.z; As[lk + 3][lr] = av.w;
        *(float4*)&Bs[br][bc] = bv;
        __syncthreads();
#pragma unroll
        for (int kk = 0; kk < 16; kk++) {
            float4 a  = *(const float4*)&As[kk][ty << 2];
            float4 bb = *(const float4*)&Bs[kk][tx << 2];
            acc[0][0] += a.x * bb.x; acc[0][1] += a.x * bb.y; acc[0][2] += a.x * bb.z; acc[0][3] += a.x * bb.w;
            acc[1][0] += a.y * bb.x; acc[1][1] += a.y * bb.y; acc[1][2] += a.y * bb.z; acc[1][3] += a.y * bb.w;
            acc[2][0] += a.z * bb.x; acc[2][1] += a.z * bb.y; acc[2][2] += a.z * bb.z; acc[2][3] += a.z * bb.w;
            acc[3][0] += a.w * bb.x; acc[3][1] += a.w * bb.y; acc[3][2] += a.w * bb.z; acc[3][3] += a.w * bb.w;
        }
        __syncthreads();
    }
#pragma unroll
    for (int i = 0; i < 4; i++) {
        int grow = m0 + (ty << 2) + i;
        float4 o;
        o.x = acc[i][0]; o.y = acc[i][1]; o.z = acc[i][2]; o.w = acc[i][3];
        *(float4*)&g_uh[(size_t)grow * DD + n0 + (tx << 2)] = o;
    }
}

// ============================================================
// sentence-level scores
// ============================================================
__global__ __launch_bounds__(128) void sent_kernel(const float* __restrict__ v_sent)
{
    int row = blockIdx.x;          // b*50 + t
    int b = row / TD;
    int lane = threadIdx.x & 31, warp = threadIdx.x >> 5;  // 4 warps
    const float* wq = g_wq + (size_t)WQPAD * DD + (size_t)row * DD;  // set 1 = sent
#pragma unroll
    for (int jj = 0; jj < 4; jj++) {
        int j = warp * 4 + jj;
        const float* uh = g_uh + (size_t)(b * 16 + j) * DD;
        float acc = 0.f;
        for (int d = lane; d < DD; d += 32)
            acc += v_sent[d] * tanh_fast(wq[d] + uh[d]);
#pragma unroll
        for (int o = 16; o; o >>= 1) acc += __shfl_xor_sync(0xffffffffu, acc, o);
        if (lane == 0) g_sent[row * SENTN + j] = acc;
    }
}

// ============================================================
// main score kernel: raw partial scores (no mask / no hier), d split in halves
// grid (13 j-tiles of 80, 4 t-tiles of 16, 8 = b*? : z&3=b, z>>2=d-half)
// ============================================================
#define SC_CHUNK 64
#define SC_STRIDE 68   // 64 + 4 pad: float4-aligned, conflict-free for row-indexed LDS.128
__global__ __launch_bounds__(256) void score_kernel(
    const float* __restrict__ v_pass, const float* __restrict__ v_word)
{
    __shared__ float wq_s[16 * SC_STRIDE];
    __shared__ float uh_s[80 * SC_STRIDE];
    __shared__ float v_s[SC_CHUNK];
    int tid = threadIdx.x;
    int jt = blockIdx.x, tt = blockIdx.y;
    int b = blockIdx.z & 3, half = blockIdx.z >> 2;
    int t0 = tt * 16;
    bool is_src = (jt < 5);
    const float* wqb = g_wq + (size_t)(is_src ? 2 : 0) * WQPAD * DD + (size_t)(b * TD) * DD;
    int uh0 = is_src ? (64 + b * SRCN + jt * 80) : (1664 + b * 640 + (jt - 5) * 80);
    const float* v = is_src ? v_pass : v_word;
    int d_base = half * 256;

    int tx = tid & 15, ty = tid >> 4;
    float acc[5] = {0.f, 0.f, 0.f, 0.f, 0.f};

    for (int c = 0; c < 4; c++) {
        int d0 = d_base + c * SC_CHUNK;
        __syncthreads();
        {   // wq tile: 16 rows x 64 cols = 256 float4, one per thread
            int r = tid >> 4, col = (tid & 15) << 2;
            *(float4*)&wq_s[r * SC_STRIDE + col] =
                *(const float4*)&wqb[(size_t)(t0 + r) * DD + d0 + col];
        }
        // uh tile: 80 rows x 64 cols = 1280 float4, 5 per thread
        for (int i = tid; i < 80 * 16; i += 256) {
            int r = i >> 4, col = (i & 15) << 2;
            *(float4*)&uh_s[r * SC_STRIDE + col] =
                *(const float4*)&g_uh[(size_t)(uh0 + r) * DD + d0 + col];
        }
        if (tid < SC_CHUNK) v_s[tid] = v[d0 + tid];
        __syncthreads();
#pragma unroll 4
        for (int d4 = 0; d4 < 16; d4++) {
            float4 w4 = *(const float4*)&wq_s[ty * SC_STRIDE + (d4 << 2)];
            float4 v4 = *(const float4*)&v_s[d4 << 2];
#pragma unroll
            for (int u = 0; u < 5; u++) {
                float4 u4 = *(const float4*)&uh_s[(tx + 16 * u) * SC_STRIDE + (d4 << 2)];
                acc[u] += v4.x * tanh_fast(w4.x + u4.x);
                acc[u] += v4.y * tanh_fast(w4.y + u4.y);
                acc[u] += v4.z * tanh_fast(w4.z + u4.z);
                acc[u] += v4.w * tanh_fast(w4.w + u4.w);
            }
        }
    }

    int t = t0 + ty;
    if (t < TD) {
        float* arow = (half ? g_align1 : g_align0) + (size_t)(b * TD + t) * SJ;
        int jcol0 = is_src ? jt * 80 : SRCN + (jt - 5) * 80;
#pragma unroll
        for (int u = 0; u < 5; u++)
            arow[jcol0 + tx + 16 * u] = acc[u];
    }
}

// ============================================================
// softmax: combine d-halves, hier multiply, mask, softmax (per b,t row)
// ============================================================
__global__ __launch_bounds__(256) void softmax_kernel(
    const int* __restrict__ src_len, const int* __restrict__ word_len)
{
    __shared__ float sval[SJ];
    __shared__ float red[256];
    __shared__ float sents[SENTN];
    int row = blockIdx.x, tid = threadIdx.x;
    int b = row / TD;
    if (tid < SENTN) sents[tid] = g_sent[row * SENTN + tid];
    __syncthreads();
    int sl = src_len[b];
    for (int j = tid; j < SJ; j += 256) {
        float rv = g_align0[(size_t)row * SJ + j] + g_align1[(size_t)row * SJ + j];
        float val;
        if (j < SRCN) {
            val = (j < sl) ? rv : -1e30f;
        } else {
            int jw = j - SRCN; int s = jw / WORDN, w = jw - s * WORDN;
            val = (w < word_len[b * SENTN + s]) ? rv * sents[s] : -1e30f;
        }
        sval[j] = val;
    }
    __syncthreads();
    float m = -3.4e38f;
    for (int j = tid; j < SJ; j += 256) m = fmaxf(m, sval[j]);
    red[tid] = m; __syncthreads();
    for (int o = 128; o; o >>= 1) { if (tid < o) red[tid] = fmaxf(red[tid], red[tid + o]); __syncthreads(); }
    m = red[0]; __syncthreads();
    float s = 0.f;
    for (int j = tid; j < SJ; j += 256) { float e = __expf(sval[j] - m); sval[j] = e; s += e; }
    red[tid] = s; __syncthreads();
    for (int o = 128; o; o >>= 1) { if (tid < o) red[tid] += red[tid + o]; __syncthreads(); }
    float inv = 1.0f / red[0];
    for (int j = tid; j < SJ; j += 256) g_p[(size_t)row * SJ + j] = sval[j] * inv;
}

// ============================================================
// context: c[b,t,d] = sum_j p[b,t,j] * mem[b,j,d]   (gathered GEMM)
// ============================================================
__global__ __launch_bounds__(256) void context_kernel(
    const float* __restrict__ srcb, const float* __restrict__ wordb, float* __restrict__ out)
{
    __shared__ float p_s[50 * 80];
    __shared__ float m_s[80 * 33];
    int tid = threadIdx.x;
    int b = blockIdx.y;
    int d0 = blockIdx.x * 32;
    int tx = tid & 31, ty = tid >> 5;   // 32 x 8
    float acc[7] = {};

    for (int j0 = 0; j0 < SJ; j0 += 80) {
        __syncthreads();
        for (int i = tid; i < 50 * 80; i += 256) {
            int r = i / 80, c = i - r * 80;
            p_s[i] = g_p[(size_t)(b * TD + r) * SJ + j0 + c];
        }
        for (int i = tid; i < 80 * 32; i += 256) {
            int r = i >> 5, c = i & 31;
            int j = j0 + r;
            const float* mp;
            if (j < SRCN) mp = srcb + (size_t)(j * BD + b) * DD;
            else { int jw = j - SRCN; int s = jw / WORDN, w = jw - s * WORDN;
                   mp = wordb + (size_t)((w * BD + b) * SENTN + s) * DD; }
            m_s[r * 33 + c] = mp[d0 + c];
        }
        __syncthreads();
        for (int j = 0; j < 80; j++) {
            float mv = m_s[j * 33 + tx];
#pragma unroll
            for (int q = 0; q < 7; q++) {
                int t = ty + (q << 3);
                if (t < TD) acc[q] += p_s[t * 80 + j] * mv;
            }
        }
    }
#pragma unroll
    for (int q = 0; q < 7; q++) {
        int t = ty + (q << 3);
        if (t < TD) out[(size_t)(b * TD + t) * DD + d0 + tx] = acc[q];
    }
}

// ============================================================
extern "C" void kernel_launch(void* const* d_in, const int* in_sizes, int n_in,
                              void* d_out, int out_size)
{
    const float* source    = (const float*)d_in[0];
    const float* src_bank  = (const float*)d_in[1];
    const int*   src_len   = (const int*)  d_in[2];
    const float* sent_bank = (const float*)d_in[3];
    // d_in[4] = qa_sent_lengths (unused, matches reference)
    const float* word_bank = (const float*)d_in[5];
    const int*   word_len  = (const int*)  d_in[6];
    const float* Wq_word = (const float*)d_in[7];
    const float* bq_word = (const float*)d_in[8];
    const float* Uc_word = (const float*)d_in[9];
    const float* v_word  = (const float*)d_in[10];
    const float* Wq_sent = (const float*)d_in[11];
    const float* bq_sent = (const float*)d_in[12];
    const float* Uc_sent = (const float*)d_in[13];
    const float* v_sent  = (const float*)d_in[14];
    const float* Wq_pass = (const float*)d_in[15];
    const float* bq_pass = (const float*)d_in[16];
    const float* Uc_pass = (const float*)d_in[17];
    const float* v_pass  = (const float*)d_in[18];
    float* out = (float*)d_out;

    wq_gemm<<<dim3(8, 12), 256>>>(source, Wq_word, Wq_sent, Wq_pass, bq_word, bq_sent, bq_pass);
    uh_gemm<<<dim3(8, 66), 256>>>(sent_bank, src_bank, word_bank, Uc_sent, Uc_pass, Uc_word);
    sent_kernel<<<200, 128>>>(v_sent);
    score_kernel<<<dim3(13, 4, 8), 256>>>(v_pass, v_word);
    softmax_kernel<<<200, 256>>>(src_len, word_len);
    context_kernel<<<dim3(16, 4), 256>>>(src_bank, word_bank, out);
}